// round 12
// baseline (speedup 1.0000x reference)
#include <cuda_runtime.h>
#include <cuda_bf16.h>
#include <stdint.h>
#include <math.h>

#define NN   30000
#define EE   510000
#define TT   2
#define FIN  128
#define H1C  128
#define OUTC 64

// ---------------- scratch (device globals; no allocation) ----------------
__device__ float g_h[TT][NN * 256];        // per-snapshot h = x@W (fp32)
__device__ float g_dia[2][TT][NN];         // [layer][t][node] <h, a_i>
__device__ float g_dja[2][TT][NN];         // [layer][t][node] <h, a_j>
__device__ int   g_deg[TT][NN];
__device__ int   g_cursor[TT][NN];
__device__ int   g_rowptr[TT][NN + 1];
__device__ int   g_csr_src[TT][EE];
__device__ float g_mu1[TT][NN * H1C];
__device__ float g_mu2[TT][NN * OUTC];
__device__ float g_ixz;
__device__ float g_skl;
// weights as bf16 hi/lo in per-lane mma-fragment order
__device__ uint32_t g_B1h[256 * 64];
__device__ uint32_t g_B1l[256 * 64];
__device__ uint32_t g_B2h[128 * 64];
__device__ uint32_t g_B2l[128 * 64];

// ---------------- mma.sync + f32x2 helpers ----------------
__device__ __forceinline__ void mma16816(float* c, const uint32_t* a, const uint32_t* b) {
    asm volatile(
        "mma.sync.aligned.m16n8k16.row.col.f32.bf16.bf16.f32 "
        "{%0,%1,%2,%3}, {%4,%5,%6,%7}, {%8,%9}, {%0,%1,%2,%3};"
        : "+f"(c[0]), "+f"(c[1]), "+f"(c[2]), "+f"(c[3])
        : "r"(a[0]), "r"(a[1]), "r"(a[2]), "r"(a[3]), "r"(b[0]), "r"(b[1]));
}
// packed fp32x2 fma: acc = m * a2 + acc (PTX ISA 8.6, sm_100 family)
__device__ __forceinline__ void ffma2(unsigned long long& acc, unsigned long long m,
                                      unsigned long long a2) {
    asm("fma.rn.f32x2 %0, %1, %2, %0;" : "+l"(acc) : "l"(m), "l"(a2));
}

// ---------------- setup kernels ----------------
__global__ void zero_kernel() {
    int i = blockIdx.x * blockDim.x + threadIdx.x;
    if (i < NN) {
        g_deg[0][i] = 0; g_deg[1][i] = 0;
        g_cursor[0][i] = 0; g_cursor[1][i] = 0;
        g_dia[0][0][i] = 0.f; g_dia[0][1][i] = 0.f;
        g_dia[1][0][i] = 0.f; g_dia[1][1][i] = 0.f;
        g_dja[0][0][i] = 0.f; g_dja[0][1][i] = 0.f;
        g_dja[1][0][i] = 0.f; g_dja[1][1][i] = 0.f;
    }
    if (i == 0) { g_ixz = 0.f; g_skl = 0.f; }
}

__global__ void hist2_kernel(const int* __restrict__ ei) {
    int i = blockIdx.x * blockDim.x + threadIdx.x;
    if (i < 2 * EE) {
        int t = (i >= EE) ? 1 : 0;
        int e = i - t * EE;
        int d = ei[(size_t)t * 2 * EE + EE + e];
        atomicAdd(&g_deg[t][d], 1);
    }
}

__global__ void scan2_kernel() {
    const int P = 30;
    int t = blockIdx.x;
    __shared__ int wsum[32];
    int tid = threadIdx.x, lane = tid & 31, wid = tid >> 5;
    int base = tid * P;
    int loc[P];
    int s = 0;
#pragma unroll
    for (int j = 0; j < P; j++) {
        int idx = base + j;
        int v = (idx < NN) ? g_deg[t][idx] : 0;
        loc[j] = s;
        s += v;
    }
    int inc = s;
#pragma unroll
    for (int o = 1; o < 32; o <<= 1) {
        int y = __shfl_up_sync(0xffffffffu, inc, o);
        if (lane >= o) inc += y;
    }
    if (lane == 31) wsum[wid] = inc;
    __syncthreads();
    if (wid == 0) {
        int w = wsum[lane];
#pragma unroll
        for (int o = 1; o < 32; o <<= 1) {
            int y = __shfl_up_sync(0xffffffffu, w, o);
            if (lane >= o) w += y;
        }
        wsum[lane] = w;
    }
    __syncthreads();
    int off = inc - s + (wid ? wsum[wid - 1] : 0);
#pragma unroll
    for (int j = 0; j < P; j++) {
        int idx = base + j;
        if (idx < NN) g_rowptr[t][idx] = off + loc[j];
    }
    if (tid == 1023) g_rowptr[t][NN] = off + s;
}

__global__ void scatter2_kernel(const int* __restrict__ ei) {
    int i = blockIdx.x * blockDim.x + threadIdx.x;
    if (i < 2 * EE) {
        int t = (i >= EE) ? 1 : 0;
        int e = i - t * EE;
        const int* src = ei + (size_t)t * 2 * EE;
        const int* dst = src + EE;
        int d = dst[e];
        int pos = g_rowptr[t][d] + atomicAdd(&g_cursor[t][d], 1);
        g_csr_src[t][pos] = src[e];
    }
}

// W fp32 [K=128, Ncols] -> bf16 hi/lo fragments (per-lane order)
__global__ void convB_kernel(const float* __restrict__ W,
                             uint32_t* __restrict__ Bh,
                             uint32_t* __restrict__ Bl, int Ncols) {
    int i = blockIdx.x * blockDim.x + threadIdx.x;
    if (i >= Ncols * 64) return;
    int l = i & 31, r = (i >> 5) & 1, s = (i >> 6) & 7, g = i >> 9;
    int n = g * 8 + (l >> 2);
    int k = s * 16 + (l & 3) * 2 + r * 8;
    float v0 = W[(size_t)k * Ncols + n];
    float v1 = W[(size_t)(k + 1) * Ncols + n];
    __nv_bfloat162 h2 = __floats2bfloat162_rn(v0, v1);
    float rx = v0 - __bfloat162float(h2.x);
    float ry = v1 - __bfloat162float(h2.y);
    __nv_bfloat162 l2 = __floats2bfloat162_rn(rx, ry);
    Bh[i] = *(uint32_t*)&h2;
    Bl[i] = *(uint32_t*)&l2;
}

// ---------------- HMMA GEMM + fused attention dots (t via blockIdx.z) ------
// C[M, NCOLS] = A[M,128] @ B ; di/dj += C-fragment . att (atomics)
template <int NCOLS>
__global__ void __launch_bounds__(256, 1)
gemm_mma(const float* __restrict__ Abase, size_t strideA,
         const uint32_t* __restrict__ Bh, const uint32_t* __restrict__ Bl,
         float* __restrict__ Cbase, size_t strideC,
         const float* __restrict__ att,
         float* __restrict__ diBase, float* __restrict__ djBase, int M) {
    extern __shared__ char smem[];
    const int AL_OFF = 34816;
    uint32_t* sBh = (uint32_t*)(smem + 69632);
    uint32_t* sBl = sBh + 8192;
    int tid = threadIdx.x, wid = tid >> 5, l = tid & 31;
    int brow = blockIdx.x * 128, bcol = blockIdx.y * 128;
    int tz = blockIdx.z;
    const float* A = Abase + (size_t)tz * strideA;
    float* Cmat = Cbase + (size_t)tz * strideC;
    float* di = diBase + (size_t)tz * NN;
    float* dj = djBase + (size_t)tz * NN;

    {
        const int4* gH = (const int4*)(Bh + (size_t)blockIdx.y * 16 * 512);
        const int4* gL = (const int4*)(Bl + (size_t)blockIdx.y * 16 * 512);
        int4* dH = (int4*)sBh;
        int4* dL = (int4*)sBl;
        for (int i = tid; i < 2048; i += 256) { dH[i] = gH[i]; dL[i] = gL[i]; }
    }
    for (int i = tid; i < 128 * 64; i += 256) {
        int row = i >> 6, kp = i & 63;
        int gr = brow + row;
        float2 v = make_float2(0.f, 0.f);
        if (gr < M) v = *(const float2*)(A + (size_t)gr * 128 + kp * 2);
        __nv_bfloat162 h2 = __floats2bfloat162_rn(v.x, v.y);
        float rx = v.x - __bfloat162float(h2.x);
        float ry = v.y - __bfloat162float(h2.y);
        __nv_bfloat162 l2 = __floats2bfloat162_rn(rx, ry);
        int hoff = row * 136 + kp * 2;
        *(uint32_t*)(smem + hoff * 2) = *(uint32_t*)&h2;
        *(uint32_t*)(smem + AL_OFF + hoff * 2) = *(uint32_t*)&l2;
    }
    __syncthreads();

    int wm = wid >> 2, wn = wid & 3;
    float acc[4][4][4];
#pragma unroll
    for (int mt = 0; mt < 4; mt++)
#pragma unroll
        for (int nt = 0; nt < 4; nt++)
#pragma unroll
            for (int k = 0; k < 4; k++) acc[mt][nt][k] = 0.f;

    int arow = wm * 64 + (l >> 2);
    int acol = (l & 3) * 2;

    for (int s = 0; s < 8; s++) {
        uint32_t aH[4][4], aL[4][4];
#pragma unroll
        for (int mt = 0; mt < 4; mt++) {
            int r0 = arow + mt * 16;
            int c0 = s * 16 + acol;
            int o00 = (r0 * 136 + c0) * 2;
            int o10 = ((r0 + 8) * 136 + c0) * 2;
            aH[mt][0] = *(uint32_t*)(smem + o00);
            aH[mt][1] = *(uint32_t*)(smem + o10);
            aH[mt][2] = *(uint32_t*)(smem + o00 + 16);
            aH[mt][3] = *(uint32_t*)(smem + o10 + 16);
            aL[mt][0] = *(uint32_t*)(smem + AL_OFF + o00);
            aL[mt][1] = *(uint32_t*)(smem + AL_OFF + o10);
            aL[mt][2] = *(uint32_t*)(smem + AL_OFF + o00 + 16);
            aL[mt][3] = *(uint32_t*)(smem + AL_OFF + o10 + 16);
        }
        uint32_t bH[4][2], bL[4][2];
#pragma unroll
        for (int nt = 0; nt < 4; nt++) {
            int g = wn * 4 + nt;
            int base = ((g * 8 + s) * 2) * 32 + l;
            bH[nt][0] = sBh[base]; bH[nt][1] = sBh[base + 32];
            bL[nt][0] = sBl[base]; bL[nt][1] = sBl[base + 32];
        }
#pragma unroll
        for (int mt = 0; mt < 4; mt++)
#pragma unroll
            for (int nt = 0; nt < 4; nt++) {
                mma16816(acc[mt][nt], aH[mt], bH[nt]);
                mma16816(acc[mt][nt], aH[mt], bL[nt]);
                mma16816(acc[mt][nt], aL[mt], bH[nt]);
            }
    }

    // store C + fused attention dot partials
    float si0[4], si1[4], sj0[4], sj1[4];
#pragma unroll
    for (int mt = 0; mt < 4; mt++) { si0[mt] = 0.f; si1[mt] = 0.f; sj0[mt] = 0.f; sj1[mt] = 0.f; }

#pragma unroll
    for (int nt = 0; nt < 4; nt++) {
        int c0 = bcol + wn * 32 + nt * 8 + (l & 3) * 2;
        float ai0 = att[c0], ai1 = att[c0 + 1];
        float aj0 = att[NCOLS + c0], aj1 = att[NCOLS + c0 + 1];
#pragma unroll
        for (int mt = 0; mt < 4; mt++) {
            si0[mt] += acc[mt][nt][0] * ai0 + acc[mt][nt][1] * ai1;
            si1[mt] += acc[mt][nt][2] * ai0 + acc[mt][nt][3] * ai1;
            sj0[mt] += acc[mt][nt][0] * aj0 + acc[mt][nt][1] * aj1;
            sj1[mt] += acc[mt][nt][2] * aj0 + acc[mt][nt][3] * aj1;
        }
    }
#pragma unroll
    for (int mt = 0; mt < 4; mt++) {
        si0[mt] += __shfl_xor_sync(0xffffffffu, si0[mt], 1);
        si0[mt] += __shfl_xor_sync(0xffffffffu, si0[mt], 2);
        si1[mt] += __shfl_xor_sync(0xffffffffu, si1[mt], 1);
        si1[mt] += __shfl_xor_sync(0xffffffffu, si1[mt], 2);
        sj0[mt] += __shfl_xor_sync(0xffffffffu, sj0[mt], 1);
        sj0[mt] += __shfl_xor_sync(0xffffffffu, sj0[mt], 2);
        sj1[mt] += __shfl_xor_sync(0xffffffffu, sj1[mt], 1);
        sj1[mt] += __shfl_xor_sync(0xffffffffu, sj1[mt], 2);
    }

#pragma unroll
    for (int mt = 0; mt < 4; mt++) {
        int r0 = brow + wm * 64 + mt * 16 + (l >> 2);
#pragma unroll
        for (int nt = 0; nt < 4; nt++) {
            int c0 = bcol + wn * 32 + nt * 8 + (l & 3) * 2;
            if (r0 < M)
                *(float2*)(Cmat + (size_t)r0 * NCOLS + c0) =
                    make_float2(acc[mt][nt][0], acc[mt][nt][1]);
            if (r0 + 8 < M)
                *(float2*)(Cmat + (size_t)(r0 + 8) * NCOLS + c0) =
                    make_float2(acc[mt][nt][2], acc[mt][nt][3]);
        }
        if ((l & 3) == 0) {
            if (r0 < M) { atomicAdd(&di[r0], si0[mt]); atomicAdd(&dj[r0], sj0[mt]); }
            if (r0 + 8 < M) { atomicAdd(&di[r0 + 8], si1[mt]); atomicAdd(&dj[r0 + 8], sj1[mt]); }
        }
    }
}

// ---------------- fused aggregation (min-issue loop: LDS.64 + f32x2 FMA) ----
// t via blockIdx.y
template <int C>
__global__ void __launch_bounds__(256)
agg_kernel(const float* __restrict__ hBase, size_t strideH,
           const float* __restrict__ bvec,
           const float* __restrict__ diBase, const float* __restrict__ djBase,
           float* __restrict__ muBase) {
    constexpr int PL = C / 32;
    __shared__ uint2 s_pair[8][32];    // (idx, alpha bits)
    int t = blockIdx.y;
    int w = threadIdx.x >> 5;
    int gw = blockIdx.x * 8 + w;
    int lane = threadIdx.x & 31;
    if (gw >= NN) return;
    const float* h = hBase + (size_t)t * strideH;
    const float* di = diBase + (size_t)t * NN;
    const float* dj = djBase + (size_t)t * NN;
    float* mu_out = muBase + (size_t)t * NN * C;

    int beg = g_rowptr[t][gw], end = g_rowptr[t][gw + 1];
    float dvi = di[gw];
    float invdeg = 1.f / (float)(end - beg);
    float bM[PL], bS[PL];
#pragma unroll
    for (int k = 0; k < PL; k++) {
        bM[k] = bvec[lane * PL + k];
        bS[k] = bvec[C + lane * PL + k];
    }
    unsigned long long accMa = 0ull, accMb = 0ull, accSa = 0ull, accSb = 0ull;
    float skl = 0.f;
    const float q = 1.f / (1.f + expf(-(1.f / 15.f)));
    const float logq = logf(q), log1mq = logf(1.f - q);

    for (int base = beg; base < end; base += 32) {
        int n = min(32, end - base);
        // lane-parallel: resolve indices + attention for up to 32 edges at once
        if (lane < n) {
            int idx = g_csr_src[t][base + lane];
            float lg = dvi + dj[idx];
            lg = lg > 0.f ? lg : 0.2f * lg;
            float p = 1.f / (1.f + __expf(-lg));
            p = fminf(fmaxf(p, 0.01f), 0.99f);
            float alpha = p * invdeg;
            skl += p * (__logf(p) - logq) + (1.f - p) * (__logf(1.f - p) - log1mq);
            s_pair[w][lane] = make_uint2((unsigned)idx, __float_as_uint(alpha));
        }
        __syncwarp();
        if constexpr (PL == 4) {
#pragma unroll 4
            for (int j = 0; j < n; j++) {
                uint2 pk = s_pair[w][j];
                const float* hr = h + (size_t)pk.x * (2 * C);
                ulonglong2 mr = __ldcg((const ulonglong2*)(hr + lane * 4));
                ulonglong2 sr = __ldcg((const ulonglong2*)(hr + C + lane * 4));
                unsigned long long a2;
                asm("mov.b64 %0, {%1, %1};" : "=l"(a2) : "r"(pk.y));
                ffma2(accMa, mr.x, a2); ffma2(accMb, mr.y, a2);
                ffma2(accSa, sr.x, a2); ffma2(accSb, sr.y, a2);
            }
        } else {
#pragma unroll 4
            for (int j = 0; j < n; j++) {
                uint2 pk = s_pair[w][j];
                const float* hr = h + (size_t)pk.x * (2 * C);
                unsigned long long mr = __ldcg((const unsigned long long*)(hr + lane * 2));
                unsigned long long sr = __ldcg((const unsigned long long*)(hr + C + lane * 2));
                unsigned long long a2;
                asm("mov.b64 %0, {%1, %1};" : "=l"(a2) : "r"(pk.y));
                ffma2(accMa, mr, a2);
                ffma2(accSa, sr, a2);
            }
        }
        __syncwarp();
    }

    float accM[PL], accS[PL];
    asm("mov.b64 {%0, %1}, %2;" : "=f"(accM[0]), "=f"(accM[1]) : "l"(accMa));
    asm("mov.b64 {%0, %1}, %2;" : "=f"(accS[0]), "=f"(accS[1]) : "l"(accSa));
    if constexpr (PL == 4) {
        asm("mov.b64 {%0, %1}, %2;" : "=f"(accM[2]), "=f"(accM[3]) : "l"(accMb));
        asm("mov.b64 {%0, %1}, %2;" : "=f"(accS[2]), "=f"(accS[3]) : "l"(accSb));
    }
#pragma unroll
    for (int k = 0; k < PL; k++) {
        accM[k] += bM[k];
        accS[k] += bS[k];
    }
    if constexpr (PL == 4) {
        *(float4*)(mu_out + (size_t)gw * C + lane * 4) =
            make_float4(accM[0], accM[1], accM[2], accM[3]);
    } else {
        *(float2*)(mu_out + (size_t)gw * C + lane * 2) =
            make_float2(accM[0], accM[1]);
    }
    float kls = 0.f;
#pragma unroll
    for (int k = 0; k < PL; k++) {
        float x = accS[k];
        float sp = fmaxf(x, 0.f) + __logf(1.f + __expf(-fabsf(x)));   // softplus
        float sd = sp + 1e-10f;
        float m = accM[k];
        kls += -__logf(sd) + 0.5f * (sd * sd + m * m) - 0.5f;
    }
#pragma unroll
    for (int off = 16; off; off >>= 1) {
        kls += __shfl_xor_sync(0xffffffffu, kls, off);
        skl += __shfl_xor_sync(0xffffffffu, skl, off);
    }
    if (lane == 0) { atomicAdd(&g_ixz, kls); atomicAdd(&g_skl, skl); }
}

// ---------------- temporal fusion ----------------
__global__ void fuse_relu_kernel(float* __restrict__ mu1) {
    size_t i = (size_t)blockIdx.x * blockDim.x + threadIdx.x;
    const size_t total = (size_t)NN * H1C;
    if (i < total) {
        float a = mu1[i], b = mu1[total + i];
        mu1[i] = fmaxf(a, 0.f);
        mu1[total + i] = fmaxf(0.4f * a + 0.2f * b, 0.f);
    }
}

__global__ void final_kernel(const float* __restrict__ mu2,
                             float* __restrict__ out, int out_size) {
    int i = blockIdx.x * blockDim.x + threadIdx.x;
    const int total = NN * OUTC;
    if (i < total) {
        float a = mu2[i], b = mu2[total + i];
        if (i < out_size) out[i] = a;
        if (total + i < out_size) out[total + i] = 0.4f * a + 0.2f * b;
    }
    if (i == 0) {
        if (2 * total < out_size)     out[2 * total]     = g_ixz / (4.0f * NN);
        if (2 * total + 1 < out_size) out[2 * total + 1] = g_skl / (4.0f * EE);
    }
}

// ---------------- launch ----------------
extern "C" void kernel_launch(void* const* d_in, const int* in_sizes, int n_in,
                              void* d_out, int out_size) {
    const float* x_all = (const float*)d_in[0];
    const int*   ei    = (const int*)d_in[1];
    const float* W1    = (const float*)d_in[2];
    const float* att1  = (const float*)d_in[3];
    const float* b1    = (const float*)d_in[4];
    const float* W2    = (const float*)d_in[5];
    const float* att2  = (const float*)d_in[6];
    const float* b2    = (const float*)d_in[7];
    float* out = (float*)d_out;

    float *p_h0, *p_mu1, *p_mu2, *p_dia, *p_dja;
    cudaGetSymbolAddress((void**)&p_h0, g_h);
    cudaGetSymbolAddress((void**)&p_mu1, g_mu1);
    cudaGetSymbolAddress((void**)&p_mu2, g_mu2);
    cudaGetSymbolAddress((void**)&p_dia, g_dia);
    cudaGetSymbolAddress((void**)&p_dja, g_dja);
    float* p_diL[2] = {p_dia, p_dia + 2 * NN};
    float* p_djL[2] = {p_dja, p_dja + 2 * NN};
    uint32_t *p_B1h, *p_B1l, *p_B2h, *p_B2l;
    cudaGetSymbolAddress((void**)&p_B1h, g_B1h);
    cudaGetSymbolAddress((void**)&p_B1l, g_B1l);
    cudaGetSymbolAddress((void**)&p_B2h, g_B2h);
    cudaGetSymbolAddress((void**)&p_B2l, g_B2l);

    const int GSMEM = 69632 + 2 * 8192 * 4;   // 135168 bytes
    static bool attr_done = false;
    if (!attr_done) {
        cudaFuncSetAttribute(gemm_mma<256>, cudaFuncAttributeMaxDynamicSharedMemorySize, GSMEM);
        cudaFuncSetAttribute(gemm_mma<128>, cudaFuncAttributeMaxDynamicSharedMemorySize, GSMEM);
        attr_done = true;
    }

    int gBlocks = (NN + 127) / 128;
    int warpBlocks = (NN + 7) / 8;

    // reorder: gemm256 is the 4th launch -> ncu captures it
    convB_kernel<<<(256 * 64 + 255) / 256, 256>>>(W1, p_B1h, p_B1l, 256);   // 1
    zero_kernel<<<(NN + 255) / 256, 256>>>();                               // 2
    hist2_kernel<<<(2 * EE + 255) / 256, 256>>>(ei);                        // 3
    gemm_mma<256><<<dim3(gBlocks, 2, 2), 256, GSMEM>>>(                      // 4 (profiled)
        x_all, (size_t)NN * FIN, p_B1h, p_B1l, p_h0, (size_t)NN * 256,
        att1, p_diL[0], p_djL[0], NN);
    scan2_kernel<<<2, 1024>>>();                                            // 5
    scatter2_kernel<<<(2 * EE + 255) / 256, 256>>>(ei);                     // 6
    convB_kernel<<<(128 * 64 + 255) / 256, 256>>>(W2, p_B2h, p_B2l, 128);   // 7
    agg_kernel<H1C><<<dim3(warpBlocks, 2), 256>>>(                          // 8
        p_h0, (size_t)NN * 256, b1, p_diL[0], p_djL[0], p_mu1);
    fuse_relu_kernel<<<(NN * H1C + 255) / 256, 256>>>(p_mu1);               // 9
    gemm_mma<128><<<dim3(gBlocks, 1, 2), 256, GSMEM>>>(                      // 10
        p_mu1, (size_t)NN * H1C, p_B2h, p_B2l, p_h0, (size_t)NN * 256,
        att2, p_diL[1], p_djL[1], NN);
    agg_kernel<OUTC><<<dim3(warpBlocks, 2), 256>>>(                         // 11
        p_h0, (size_t)NN * 256, b2, p_diL[1], p_djL[1], p_mu2);
    final_kernel<<<(NN * OUTC + 255) / 256, 256>>>(p_mu2, out, out_size);   // 12
}

// round 13
// speedup vs baseline: 1.1054x; 1.1054x over previous
#include <cuda_runtime.h>
#include <cuda_bf16.h>
#include <stdint.h>
#include <math.h>

#define NN   30000
#define EE   510000
#define TT   2
#define FIN  128
#define H1C  128
#define OUTC 64

// ---------------- scratch (device globals; no allocation) ----------------
__device__ float g_h[TT][NN * 256];        // per-snapshot h = x@W (fp32)
__device__ float g_dia[2][TT][NN];         // [layer][t][node] <h, a_i>
__device__ float g_dja[2][TT][NN];         // [layer][t][node] <h, a_j>
__device__ int   g_deg[TT][NN];
__device__ int   g_cursor[TT][NN];
__device__ int   g_rowptr[TT][NN + 1];
__device__ int   g_csr_src[TT][EE];
__device__ float g_mu1[TT][NN * H1C];
__device__ float g_mu2[TT][NN * OUTC];
__device__ float g_ixz;
__device__ float g_skl;
// weights as bf16 hi/lo in per-lane mma-fragment order
__device__ uint32_t g_B1h[256 * 64];
__device__ uint32_t g_B1l[256 * 64];
__device__ uint32_t g_B2h[128 * 64];
__device__ uint32_t g_B2l[128 * 64];

// ---------------- mma.sync + f32x2 helpers ----------------
__device__ __forceinline__ void mma16816(float* c, const uint32_t* a, const uint32_t* b) {
    asm volatile(
        "mma.sync.aligned.m16n8k16.row.col.f32.bf16.bf16.f32 "
        "{%0,%1,%2,%3}, {%4,%5,%6,%7}, {%8,%9}, {%0,%1,%2,%3};"
        : "+f"(c[0]), "+f"(c[1]), "+f"(c[2]), "+f"(c[3])
        : "r"(a[0]), "r"(a[1]), "r"(a[2]), "r"(a[3]), "r"(b[0]), "r"(b[1]));
}
// packed fp32x2 fma: acc = m * a2 + acc (PTX ISA 8.6, sm_100 family)
__device__ __forceinline__ void ffma2(unsigned long long& acc, unsigned long long m,
                                      unsigned long long a2) {
    asm("fma.rn.f32x2 %0, %1, %2, %0;" : "+l"(acc) : "l"(m), "l"(a2));
}

// ---------------- setup kernels ----------------
__global__ void zero_kernel() {
    int i = blockIdx.x * blockDim.x + threadIdx.x;
    if (i < NN) {
        g_deg[0][i] = 0; g_deg[1][i] = 0;
        g_cursor[0][i] = 0; g_cursor[1][i] = 0;
        g_dia[0][0][i] = 0.f; g_dia[0][1][i] = 0.f;
        g_dia[1][0][i] = 0.f; g_dia[1][1][i] = 0.f;
        g_dja[0][0][i] = 0.f; g_dja[0][1][i] = 0.f;
        g_dja[1][0][i] = 0.f; g_dja[1][1][i] = 0.f;
    }
    if (i == 0) { g_ixz = 0.f; g_skl = 0.f; }
}

__global__ void hist2_kernel(const int* __restrict__ ei) {
    int i = blockIdx.x * blockDim.x + threadIdx.x;
    if (i < 2 * EE) {
        int t = (i >= EE) ? 1 : 0;
        int e = i - t * EE;
        int d = ei[(size_t)t * 2 * EE + EE + e];
        atomicAdd(&g_deg[t][d], 1);
    }
}

__global__ void scan2_kernel() {
    const int P = 30;
    int t = blockIdx.x;
    __shared__ int wsum[32];
    int tid = threadIdx.x, lane = tid & 31, wid = tid >> 5;
    int base = tid * P;
    int loc[P];
    int s = 0;
#pragma unroll
    for (int j = 0; j < P; j++) {
        int idx = base + j;
        int v = (idx < NN) ? g_deg[t][idx] : 0;
        loc[j] = s;
        s += v;
    }
    int inc = s;
#pragma unroll
    for (int o = 1; o < 32; o <<= 1) {
        int y = __shfl_up_sync(0xffffffffu, inc, o);
        if (lane >= o) inc += y;
    }
    if (lane == 31) wsum[wid] = inc;
    __syncthreads();
    if (wid == 0) {
        int w = wsum[lane];
#pragma unroll
        for (int o = 1; o < 32; o <<= 1) {
            int y = __shfl_up_sync(0xffffffffu, w, o);
            if (lane >= o) w += y;
        }
        wsum[lane] = w;
    }
    __syncthreads();
    int off = inc - s + (wid ? wsum[wid - 1] : 0);
#pragma unroll
    for (int j = 0; j < P; j++) {
        int idx = base + j;
        if (idx < NN) g_rowptr[t][idx] = off + loc[j];
    }
    if (tid == 1023) g_rowptr[t][NN] = off + s;
}

__global__ void scatter2_kernel(const int* __restrict__ ei) {
    int i = blockIdx.x * blockDim.x + threadIdx.x;
    if (i < 2 * EE) {
        int t = (i >= EE) ? 1 : 0;
        int e = i - t * EE;
        const int* src = ei + (size_t)t * 2 * EE;
        const int* dst = src + EE;
        int d = dst[e];
        int pos = g_rowptr[t][d] + atomicAdd(&g_cursor[t][d], 1);
        g_csr_src[t][pos] = src[e];
    }
}

// W fp32 [K=128, Ncols] -> bf16 hi/lo fragments (per-lane order)
__global__ void convB_kernel(const float* __restrict__ W,
                             uint32_t* __restrict__ Bh,
                             uint32_t* __restrict__ Bl, int Ncols) {
    int i = blockIdx.x * blockDim.x + threadIdx.x;
    if (i >= Ncols * 64) return;
    int l = i & 31, r = (i >> 5) & 1, s = (i >> 6) & 7, g = i >> 9;
    int n = g * 8 + (l >> 2);
    int k = s * 16 + (l & 3) * 2 + r * 8;
    float v0 = W[(size_t)k * Ncols + n];
    float v1 = W[(size_t)(k + 1) * Ncols + n];
    __nv_bfloat162 h2 = __floats2bfloat162_rn(v0, v1);
    float rx = v0 - __bfloat162float(h2.x);
    float ry = v1 - __bfloat162float(h2.y);
    __nv_bfloat162 l2 = __floats2bfloat162_rn(rx, ry);
    Bh[i] = *(uint32_t*)&h2;
    Bl[i] = *(uint32_t*)&l2;
}

// ---------------- HMMA GEMM + fused attention dots (t via blockIdx.z) ------
// C[M, NCOLS] = A[M,128] @ B ; di/dj += C-fragment . att (atomics)
// B fragments read directly from global (coalesced, L1/L2-resident) -> smem = A only
// -> 69.6 KB smem + 128 regs = 2 CTAs/SM
template <int NCOLS>
__global__ void __launch_bounds__(256, 2)
gemm_mma(const float* __restrict__ Abase, size_t strideA,
         const uint32_t* __restrict__ Bh, const uint32_t* __restrict__ Bl,
         float* __restrict__ Cbase, size_t strideC,
         const float* __restrict__ att,
         float* __restrict__ diBase, float* __restrict__ djBase, int M) {
    extern __shared__ char smem[];
    const int AL_OFF = 34816;
    int tid = threadIdx.x, wid = tid >> 5, l = tid & 31;
    int brow = blockIdx.x * 128, bcol = blockIdx.y * 128;
    int tz = blockIdx.z;
    const float* A = Abase + (size_t)tz * strideA;
    float* Cmat = Cbase + (size_t)tz * strideC;
    float* di = diBase + (size_t)tz * NN;
    float* dj = djBase + (size_t)tz * NN;
    const uint32_t* gBh = Bh + (size_t)blockIdx.y * 16 * 512;
    const uint32_t* gBl = Bl + (size_t)blockIdx.y * 16 * 512;

    // A: load fp32, split hi/lo, store to padded smem
    for (int i = tid; i < 128 * 64; i += 256) {
        int row = i >> 6, kp = i & 63;
        int gr = brow + row;
        float2 v = make_float2(0.f, 0.f);
        if (gr < M) v = *(const float2*)(A + (size_t)gr * 128 + kp * 2);
        __nv_bfloat162 h2 = __floats2bfloat162_rn(v.x, v.y);
        float rx = v.x - __bfloat162float(h2.x);
        float ry = v.y - __bfloat162float(h2.y);
        __nv_bfloat162 l2 = __floats2bfloat162_rn(rx, ry);
        int hoff = row * 136 + kp * 2;
        *(uint32_t*)(smem + hoff * 2) = *(uint32_t*)&h2;
        *(uint32_t*)(smem + AL_OFF + hoff * 2) = *(uint32_t*)&l2;
    }
    __syncthreads();

    int wm = wid >> 2, wn = wid & 3;
    float acc[4][4][4];
#pragma unroll
    for (int mt = 0; mt < 4; mt++)
#pragma unroll
        for (int nt = 0; nt < 4; nt++)
#pragma unroll
            for (int k = 0; k < 4; k++) acc[mt][nt][k] = 0.f;

    int arow = wm * 64 + (l >> 2);
    int acol = (l & 3) * 2;

    for (int s = 0; s < 8; s++) {
        // B fragments straight from global (coalesced 128B per load, hot in L1)
        uint32_t bH[4][2], bL[4][2];
#pragma unroll
        for (int nt = 0; nt < 4; nt++) {
            int g = wn * 4 + nt;
            int base = ((g * 8 + s) * 2) * 32 + l;
            bH[nt][0] = gBh[base]; bH[nt][1] = gBh[base + 32];
            bL[nt][0] = gBl[base]; bL[nt][1] = gBl[base + 32];
        }
        uint32_t aH[4][4], aL[4][4];
#pragma unroll
        for (int mt = 0; mt < 4; mt++) {
            int r0 = arow + mt * 16;
            int c0 = s * 16 + acol;
            int o00 = (r0 * 136 + c0) * 2;
            int o10 = ((r0 + 8) * 136 + c0) * 2;
            aH[mt][0] = *(uint32_t*)(smem + o00);
            aH[mt][1] = *(uint32_t*)(smem + o10);
            aH[mt][2] = *(uint32_t*)(smem + o00 + 16);
            aH[mt][3] = *(uint32_t*)(smem + o10 + 16);
            aL[mt][0] = *(uint32_t*)(smem + AL_OFF + o00);
            aL[mt][1] = *(uint32_t*)(smem + AL_OFF + o10);
            aL[mt][2] = *(uint32_t*)(smem + AL_OFF + o00 + 16);
            aL[mt][3] = *(uint32_t*)(smem + AL_OFF + o10 + 16);
        }
#pragma unroll
        for (int mt = 0; mt < 4; mt++)
#pragma unroll
            for (int nt = 0; nt < 4; nt++) {
                mma16816(acc[mt][nt], aH[mt], bH[nt]);
                mma16816(acc[mt][nt], aH[mt], bL[nt]);
                mma16816(acc[mt][nt], aL[mt], bH[nt]);
            }
    }

    // store C + fused attention dot partials
    float si0[4], si1[4], sj0[4], sj1[4];
#pragma unroll
    for (int mt = 0; mt < 4; mt++) { si0[mt] = 0.f; si1[mt] = 0.f; sj0[mt] = 0.f; sj1[mt] = 0.f; }

#pragma unroll
    for (int nt = 0; nt < 4; nt++) {
        int c0 = bcol + wn * 32 + nt * 8 + (l & 3) * 2;
        float ai0 = att[c0], ai1 = att[c0 + 1];
        float aj0 = att[NCOLS + c0], aj1 = att[NCOLS + c0 + 1];
#pragma unroll
        for (int mt = 0; mt < 4; mt++) {
            si0[mt] += acc[mt][nt][0] * ai0 + acc[mt][nt][1] * ai1;
            si1[mt] += acc[mt][nt][2] * ai0 + acc[mt][nt][3] * ai1;
            sj0[mt] += acc[mt][nt][0] * aj0 + acc[mt][nt][1] * aj1;
            sj1[mt] += acc[mt][nt][2] * aj0 + acc[mt][nt][3] * aj1;
        }
    }
#pragma unroll
    for (int mt = 0; mt < 4; mt++) {
        si0[mt] += __shfl_xor_sync(0xffffffffu, si0[mt], 1);
        si0[mt] += __shfl_xor_sync(0xffffffffu, si0[mt], 2);
        si1[mt] += __shfl_xor_sync(0xffffffffu, si1[mt], 1);
        si1[mt] += __shfl_xor_sync(0xffffffffu, si1[mt], 2);
        sj0[mt] += __shfl_xor_sync(0xffffffffu, sj0[mt], 1);
        sj0[mt] += __shfl_xor_sync(0xffffffffu, sj0[mt], 2);
        sj1[mt] += __shfl_xor_sync(0xffffffffu, sj1[mt], 1);
        sj1[mt] += __shfl_xor_sync(0xffffffffu, sj1[mt], 2);
    }

#pragma unroll
    for (int mt = 0; mt < 4; mt++) {
        int r0 = brow + wm * 64 + mt * 16 + (l >> 2);
#pragma unroll
        for (int nt = 0; nt < 4; nt++) {
            int c0 = bcol + wn * 32 + nt * 8 + (l & 3) * 2;
            if (r0 < M)
                *(float2*)(Cmat + (size_t)r0 * NCOLS + c0) =
                    make_float2(acc[mt][nt][0], acc[mt][nt][1]);
            if (r0 + 8 < M)
                *(float2*)(Cmat + (size_t)(r0 + 8) * NCOLS + c0) =
                    make_float2(acc[mt][nt][2], acc[mt][nt][3]);
        }
        if ((l & 3) == 0) {
            if (r0 < M) { atomicAdd(&di[r0], si0[mt]); atomicAdd(&dj[r0], sj0[mt]); }
            if (r0 + 8 < M) { atomicAdd(&di[r0 + 8], si1[mt]); atomicAdd(&dj[r0 + 8], sj1[mt]); }
        }
    }
}

// ---------------- fused aggregation (min-issue loop: LDS.64 + f32x2 FMA) ----
// t via blockIdx.y
template <int C>
__global__ void __launch_bounds__(256)
agg_kernel(const float* __restrict__ hBase, size_t strideH,
           const float* __restrict__ bvec,
           const float* __restrict__ diBase, const float* __restrict__ djBase,
           float* __restrict__ muBase) {
    constexpr int PL = C / 32;
    __shared__ uint2 s_pair[8][32];    // (idx, alpha bits)
    int t = blockIdx.y;
    int w = threadIdx.x >> 5;
    int gw = blockIdx.x * 8 + w;
    int lane = threadIdx.x & 31;
    if (gw >= NN) return;
    const float* h = hBase + (size_t)t * strideH;
    const float* di = diBase + (size_t)t * NN;
    const float* dj = djBase + (size_t)t * NN;
    float* mu_out = muBase + (size_t)t * NN * C;

    int beg = g_rowptr[t][gw], end = g_rowptr[t][gw + 1];
    float dvi = di[gw];
    float invdeg = 1.f / (float)(end - beg);
    float bM[PL], bS[PL];
#pragma unroll
    for (int k = 0; k < PL; k++) {
        bM[k] = bvec[lane * PL + k];
        bS[k] = bvec[C + lane * PL + k];
    }
    unsigned long long accMa = 0ull, accMb = 0ull, accSa = 0ull, accSb = 0ull;
    float skl = 0.f;
    const float q = 1.f / (1.f + expf(-(1.f / 15.f)));
    const float logq = logf(q), log1mq = logf(1.f - q);

    for (int base = beg; base < end; base += 32) {
        int n = min(32, end - base);
        if (lane < n) {
            int idx = g_csr_src[t][base + lane];
            float lg = dvi + dj[idx];
            lg = lg > 0.f ? lg : 0.2f * lg;
            float p = 1.f / (1.f + __expf(-lg));
            p = fminf(fmaxf(p, 0.01f), 0.99f);
            float alpha = p * invdeg;
            skl += p * (__logf(p) - logq) + (1.f - p) * (__logf(1.f - p) - log1mq);
            s_pair[w][lane] = make_uint2((unsigned)idx, __float_as_uint(alpha));
        }
        __syncwarp();
        if constexpr (PL == 4) {
#pragma unroll 4
            for (int j = 0; j < n; j++) {
                uint2 pk = s_pair[w][j];
                const float* hr = h + (size_t)pk.x * (2 * C);
                ulonglong2 mr = __ldcg((const ulonglong2*)(hr + lane * 4));
                ulonglong2 sr = __ldcg((const ulonglong2*)(hr + C + lane * 4));
                unsigned long long a2;
                asm("mov.b64 %0, {%1, %1};" : "=l"(a2) : "r"(pk.y));
                ffma2(accMa, mr.x, a2); ffma2(accMb, mr.y, a2);
                ffma2(accSa, sr.x, a2); ffma2(accSb, sr.y, a2);
            }
        } else {
#pragma unroll 4
            for (int j = 0; j < n; j++) {
                uint2 pk = s_pair[w][j];
                const float* hr = h + (size_t)pk.x * (2 * C);
                unsigned long long mr = __ldcg((const unsigned long long*)(hr + lane * 2));
                unsigned long long sr = __ldcg((const unsigned long long*)(hr + C + lane * 2));
                unsigned long long a2;
                asm("mov.b64 %0, {%1, %1};" : "=l"(a2) : "r"(pk.y));
                ffma2(accMa, mr, a2);
                ffma2(accSa, sr, a2);
            }
        }
        __syncwarp();
    }

    float accM[PL], accS[PL];
    asm("mov.b64 {%0, %1}, %2;" : "=f"(accM[0]), "=f"(accM[1]) : "l"(accMa));
    asm("mov.b64 {%0, %1}, %2;" : "=f"(accS[0]), "=f"(accS[1]) : "l"(accSa));
    if constexpr (PL == 4) {
        asm("mov.b64 {%0, %1}, %2;" : "=f"(accM[2]), "=f"(accM[3]) : "l"(accMb));
        asm("mov.b64 {%0, %1}, %2;" : "=f"(accS[2]), "=f"(accS[3]) : "l"(accSb));
    }
#pragma unroll
    for (int k = 0; k < PL; k++) {
        accM[k] += bM[k];
        accS[k] += bS[k];
    }
    if constexpr (PL == 4) {
        *(float4*)(mu_out + (size_t)gw * C + lane * 4) =
            make_float4(accM[0], accM[1], accM[2], accM[3]);
    } else {
        *(float2*)(mu_out + (size_t)gw * C + lane * 2) =
            make_float2(accM[0], accM[1]);
    }
    float kls = 0.f;
#pragma unroll
    for (int k = 0; k < PL; k++) {
        float x = accS[k];
        float sp = fmaxf(x, 0.f) + __logf(1.f + __expf(-fabsf(x)));   // softplus
        float sd = sp + 1e-10f;
        float m = accM[k];
        kls += -__logf(sd) + 0.5f * (sd * sd + m * m) - 0.5f;
    }
#pragma unroll
    for (int off = 16; off; off >>= 1) {
        kls += __shfl_xor_sync(0xffffffffu, kls, off);
        skl += __shfl_xor_sync(0xffffffffu, skl, off);
    }
    if (lane == 0) { atomicAdd(&g_ixz, kls); atomicAdd(&g_skl, skl); }
}

// ---------------- temporal fusion ----------------
__global__ void fuse_relu_kernel(float* __restrict__ mu1) {
    size_t i = (size_t)blockIdx.x * blockDim.x + threadIdx.x;
    const size_t total = (size_t)NN * H1C;
    if (i < total) {
        float a = mu1[i], b = mu1[total + i];
        mu1[i] = fmaxf(a, 0.f);
        mu1[total + i] = fmaxf(0.4f * a + 0.2f * b, 0.f);
    }
}

__global__ void final_kernel(const float* __restrict__ mu2,
                             float* __restrict__ out, int out_size) {
    int i = blockIdx.x * blockDim.x + threadIdx.x;
    const int total = NN * OUTC;
    if (i < total) {
        float a = mu2[i], b = mu2[total + i];
        if (i < out_size) out[i] = a;
        if (total + i < out_size) out[total + i] = 0.4f * a + 0.2f * b;
    }
    if (i == 0) {
        if (2 * total < out_size)     out[2 * total]     = g_ixz / (4.0f * NN);
        if (2 * total + 1 < out_size) out[2 * total + 1] = g_skl / (4.0f * EE);
    }
}

// ---------------- launch ----------------
extern "C" void kernel_launch(void* const* d_in, const int* in_sizes, int n_in,
                              void* d_out, int out_size) {
    const float* x_all = (const float*)d_in[0];
    const int*   ei    = (const int*)d_in[1];
    const float* W1    = (const float*)d_in[2];
    const float* att1  = (const float*)d_in[3];
    const float* b1    = (const float*)d_in[4];
    const float* W2    = (const float*)d_in[5];
    const float* att2  = (const float*)d_in[6];
    const float* b2    = (const float*)d_in[7];
    float* out = (float*)d_out;

    float *p_h0, *p_mu1, *p_mu2, *p_dia, *p_dja;
    cudaGetSymbolAddress((void**)&p_h0, g_h);
    cudaGetSymbolAddress((void**)&p_mu1, g_mu1);
    cudaGetSymbolAddress((void**)&p_mu2, g_mu2);
    cudaGetSymbolAddress((void**)&p_dia, g_dia);
    cudaGetSymbolAddress((void**)&p_dja, g_dja);
    float* p_diL[2] = {p_dia, p_dia + 2 * NN};
    float* p_djL[2] = {p_dja, p_dja + 2 * NN};
    uint32_t *p_B1h, *p_B1l, *p_B2h, *p_B2l;
    cudaGetSymbolAddress((void**)&p_B1h, g_B1h);
    cudaGetSymbolAddress((void**)&p_B1l, g_B1l);
    cudaGetSymbolAddress((void**)&p_B2h, g_B2h);
    cudaGetSymbolAddress((void**)&p_B2l, g_B2l);

    const int GSMEM = 69632;   // A hi/lo only
    static bool attr_done = false;
    if (!attr_done) {
        cudaFuncSetAttribute(gemm_mma<256>, cudaFuncAttributeMaxDynamicSharedMemorySize, GSMEM);
        cudaFuncSetAttribute(gemm_mma<128>, cudaFuncAttributeMaxDynamicSharedMemorySize, GSMEM);
        attr_done = true;
    }

    int gBlocks = (NN + 127) / 128;
    int warpBlocks = (NN + 7) / 8;

    convB_kernel<<<(256 * 64 + 255) / 256, 256>>>(W1, p_B1h, p_B1l, 256);   // 1
    zero_kernel<<<(NN + 255) / 256, 256>>>();                               // 2
    hist2_kernel<<<(2 * EE + 255) / 256, 256>>>(ei);                        // 3
    gemm_mma<256><<<dim3(gBlocks, 2, 2), 256, GSMEM>>>(                      // 4 (profiled)
        x_all, (size_t)NN * FIN, p_B1h, p_B1l, p_h0, (size_t)NN * 256,
        att1, p_diL[0], p_djL[0], NN);
    scan2_kernel<<<2, 1024>>>();                                            // 5
    scatter2_kernel<<<(2 * EE + 255) / 256, 256>>>(ei);                     // 6
    convB_kernel<<<(128 * 64 + 255) / 256, 256>>>(W2, p_B2h, p_B2l, 128);   // 7
    agg_kernel<H1C><<<dim3(warpBlocks, 2), 256>>>(                          // 8
        p_h0, (size_t)NN * 256, b1, p_diL[0], p_djL[0], p_mu1);
    fuse_relu_kernel<<<(NN * H1C + 255) / 256, 256>>>(p_mu1);               // 9
    gemm_mma<128><<<dim3(gBlocks, 1, 2), 256, GSMEM>>>(                      // 10
        p_mu1, (size_t)NN * H1C, p_B2h, p_B2l, p_h0, (size_t)NN * 256,
        att2, p_diL[1], p_djL[1], NN);
    agg_kernel<OUTC><<<dim3(warpBlocks, 2), 256>>>(                         // 11
        p_h0, (size_t)NN * 256, b2, p_diL[1], p_djL[1], p_mu2);
    final_kernel<<<(NN * OUTC + 255) / 256, 256>>>(p_mu2, out, out_size);   // 12
}

// round 14
// speedup vs baseline: 1.1175x; 1.0109x over previous
#include <cuda_runtime.h>
#include <cuda_bf16.h>
#include <stdint.h>
#include <math.h>

#define NN   30000
#define EE   510000
#define TT   2
#define FIN  128
#define H1C  128
#define OUTC 64

// ---------------- scratch (device globals; no allocation) ----------------
__device__ float g_h[TT][NN * 256];        // per-snapshot h = x@W (fp32)
__device__ float g_dia[2][TT][NN];         // [layer][t][node] <h, a_i>
__device__ float g_dja[2][TT][NN];         // [layer][t][node] <h, a_j>
__device__ int   g_deg[TT][NN];
__device__ int   g_cursor[TT][NN];
__device__ int   g_rowptr[TT][NN + 1];
__device__ int   g_csr_src[TT][EE];
__device__ float g_mu1[TT][NN * H1C];
__device__ float g_mu2[TT][NN * OUTC];
__device__ float g_ixz;
__device__ float g_skl;
// weights as bf16 hi/lo in per-lane mma-fragment order
__device__ uint32_t g_B1h[256 * 64];
__device__ uint32_t g_B1l[256 * 64];
__device__ uint32_t g_B2h[128 * 64];
__device__ uint32_t g_B2l[128 * 64];

// ---------------- mma.sync + f32x2 helpers ----------------
__device__ __forceinline__ void mma16816(float* c, const uint32_t* a, const uint32_t* b) {
    asm volatile(
        "mma.sync.aligned.m16n8k16.row.col.f32.bf16.bf16.f32 "
        "{%0,%1,%2,%3}, {%4,%5,%6,%7}, {%8,%9}, {%0,%1,%2,%3};"
        : "+f"(c[0]), "+f"(c[1]), "+f"(c[2]), "+f"(c[3])
        : "r"(a[0]), "r"(a[1]), "r"(a[2]), "r"(a[3]), "r"(b[0]), "r"(b[1]));
}
// packed fp32x2 fma: acc = m * a2 + acc (PTX ISA 8.6, sm_100 family)
__device__ __forceinline__ void ffma2(unsigned long long& acc, unsigned long long m,
                                      unsigned long long a2) {
    asm("fma.rn.f32x2 %0, %1, %2, %0;" : "+l"(acc) : "l"(m), "l"(a2));
}

// ---------------- setup kernels ----------------
__global__ void zero_kernel() {
    int i = blockIdx.x * blockDim.x + threadIdx.x;
    if (i < NN) {
        g_deg[0][i] = 0; g_deg[1][i] = 0;
        g_cursor[0][i] = 0; g_cursor[1][i] = 0;
        g_dia[0][0][i] = 0.f; g_dia[0][1][i] = 0.f;
        g_dia[1][0][i] = 0.f; g_dia[1][1][i] = 0.f;
        g_dja[0][0][i] = 0.f; g_dja[0][1][i] = 0.f;
        g_dja[1][0][i] = 0.f; g_dja[1][1][i] = 0.f;
    }
    if (i == 0) { g_ixz = 0.f; g_skl = 0.f; }
}

__global__ void hist2_kernel(const int* __restrict__ ei) {
    int i = blockIdx.x * blockDim.x + threadIdx.x;
    if (i < 2 * EE) {
        int t = (i >= EE) ? 1 : 0;
        int e = i - t * EE;
        int d = ei[(size_t)t * 2 * EE + EE + e];
        atomicAdd(&g_deg[t][d], 1);
    }
}

__global__ void scan2_kernel() {
    const int P = 30;
    int t = blockIdx.x;
    __shared__ int wsum[32];
    int tid = threadIdx.x, lane = tid & 31, wid = tid >> 5;
    int base = tid * P;
    int loc[P];
    int s = 0;
#pragma unroll
    for (int j = 0; j < P; j++) {
        int idx = base + j;
        int v = (idx < NN) ? g_deg[t][idx] : 0;
        loc[j] = s;
        s += v;
    }
    int inc = s;
#pragma unroll
    for (int o = 1; o < 32; o <<= 1) {
        int y = __shfl_up_sync(0xffffffffu, inc, o);
        if (lane >= o) inc += y;
    }
    if (lane == 31) wsum[wid] = inc;
    __syncthreads();
    if (wid == 0) {
        int w = wsum[lane];
#pragma unroll
        for (int o = 1; o < 32; o <<= 1) {
            int y = __shfl_up_sync(0xffffffffu, w, o);
            if (lane >= o) w += y;
        }
        wsum[lane] = w;
    }
    __syncthreads();
    int off = inc - s + (wid ? wsum[wid - 1] : 0);
#pragma unroll
    for (int j = 0; j < P; j++) {
        int idx = base + j;
        if (idx < NN) g_rowptr[t][idx] = off + loc[j];
    }
    if (tid == 1023) g_rowptr[t][NN] = off + s;
}

__global__ void scatter2_kernel(const int* __restrict__ ei) {
    int i = blockIdx.x * blockDim.x + threadIdx.x;
    if (i < 2 * EE) {
        int t = (i >= EE) ? 1 : 0;
        int e = i - t * EE;
        const int* src = ei + (size_t)t * 2 * EE;
        const int* dst = src + EE;
        int d = dst[e];
        int pos = g_rowptr[t][d] + atomicAdd(&g_cursor[t][d], 1);
        g_csr_src[t][pos] = src[e];
    }
}

// W fp32 [K=128, Ncols] -> bf16 hi/lo fragments (per-lane order)
__global__ void convB_kernel(const float* __restrict__ W,
                             uint32_t* __restrict__ Bh,
                             uint32_t* __restrict__ Bl, int Ncols) {
    int i = blockIdx.x * blockDim.x + threadIdx.x;
    if (i >= Ncols * 64) return;
    int l = i & 31, r = (i >> 5) & 1, s = (i >> 6) & 7, g = i >> 9;
    int n = g * 8 + (l >> 2);
    int k = s * 16 + (l & 3) * 2 + r * 8;
    float v0 = W[(size_t)k * Ncols + n];
    float v1 = W[(size_t)(k + 1) * Ncols + n];
    __nv_bfloat162 h2 = __floats2bfloat162_rn(v0, v1);
    float rx = v0 - __bfloat162float(h2.x);
    float ry = v1 - __bfloat162float(h2.y);
    __nv_bfloat162 l2 = __floats2bfloat162_rn(rx, ry);
    Bh[i] = *(uint32_t*)&h2;
    Bl[i] = *(uint32_t*)&l2;
}

// ---------------- HMMA GEMM + fused attention dots (t via blockIdx.z) ------
// C[M, NCOLS] = A[M,128] @ B ; di/dj += C-fragment . att (atomics)
// B fragments read directly from global (coalesced, L1/L2-resident) -> smem = A only
// -> 69.6 KB smem + 128 regs = 2 CTAs/SM
template <int NCOLS>
__global__ void __launch_bounds__(256, 2)
gemm_mma(const float* __restrict__ Abase, size_t strideA,
         const uint32_t* __restrict__ Bh, const uint32_t* __restrict__ Bl,
         float* __restrict__ Cbase, size_t strideC,
         const float* __restrict__ att,
         float* __restrict__ diBase, float* __restrict__ djBase, int M) {
    extern __shared__ char smem[];
    const int AL_OFF = 34816;
    int tid = threadIdx.x, wid = tid >> 5, l = tid & 31;
    int brow = blockIdx.x * 128, bcol = blockIdx.y * 128;
    int tz = blockIdx.z;
    const float* A = Abase + (size_t)tz * strideA;
    float* Cmat = Cbase + (size_t)tz * strideC;
    float* di = diBase + (size_t)tz * NN;
    float* dj = djBase + (size_t)tz * NN;
    const uint32_t* gBh = Bh + (size_t)blockIdx.y * 16 * 512;
    const uint32_t* gBl = Bl + (size_t)blockIdx.y * 16 * 512;

    // A: load fp32, split hi/lo, store to padded smem
    for (int i = tid; i < 128 * 64; i += 256) {
        int row = i >> 6, kp = i & 63;
        int gr = brow + row;
        float2 v = make_float2(0.f, 0.f);
        if (gr < M) v = *(const float2*)(A + (size_t)gr * 128 + kp * 2);
        __nv_bfloat162 h2 = __floats2bfloat162_rn(v.x, v.y);
        float rx = v.x - __bfloat162float(h2.x);
        float ry = v.y - __bfloat162float(h2.y);
        __nv_bfloat162 l2 = __floats2bfloat162_rn(rx, ry);
        int hoff = row * 136 + kp * 2;
        *(uint32_t*)(smem + hoff * 2) = *(uint32_t*)&h2;
        *(uint32_t*)(smem + AL_OFF + hoff * 2) = *(uint32_t*)&l2;
    }
    __syncthreads();

    int wm = wid >> 2, wn = wid & 3;
    float acc[4][4][4];
#pragma unroll
    for (int mt = 0; mt < 4; mt++)
#pragma unroll
        for (int nt = 0; nt < 4; nt++)
#pragma unroll
            for (int k = 0; k < 4; k++) acc[mt][nt][k] = 0.f;

    int arow = wm * 64 + (l >> 2);
    int acol = (l & 3) * 2;

    for (int s = 0; s < 8; s++) {
        // B fragments straight from global (coalesced 128B per load, hot in L1)
        uint32_t bH[4][2], bL[4][2];
#pragma unroll
        for (int nt = 0; nt < 4; nt++) {
            int g = wn * 4 + nt;
            int base = ((g * 8 + s) * 2) * 32 + l;
            bH[nt][0] = gBh[base]; bH[nt][1] = gBh[base + 32];
            bL[nt][0] = gBl[base]; bL[nt][1] = gBl[base + 32];
        }
        uint32_t aH[4][4], aL[4][4];
#pragma unroll
        for (int mt = 0; mt < 4; mt++) {
            int r0 = arow + mt * 16;
            int c0 = s * 16 + acol;
            int o00 = (r0 * 136 + c0) * 2;
            int o10 = ((r0 + 8) * 136 + c0) * 2;
            aH[mt][0] = *(uint32_t*)(smem + o00);
            aH[mt][1] = *(uint32_t*)(smem + o10);
            aH[mt][2] = *(uint32_t*)(smem + o00 + 16);
            aH[mt][3] = *(uint32_t*)(smem + o10 + 16);
            aL[mt][0] = *(uint32_t*)(smem + AL_OFF + o00);
            aL[mt][1] = *(uint32_t*)(smem + AL_OFF + o10);
            aL[mt][2] = *(uint32_t*)(smem + AL_OFF + o00 + 16);
            aL[mt][3] = *(uint32_t*)(smem + AL_OFF + o10 + 16);
        }
#pragma unroll
        for (int mt = 0; mt < 4; mt++)
#pragma unroll
            for (int nt = 0; nt < 4; nt++) {
                mma16816(acc[mt][nt], aH[mt], bH[nt]);
                mma16816(acc[mt][nt], aH[mt], bL[nt]);
                mma16816(acc[mt][nt], aL[mt], bH[nt]);
            }
    }

    // store C + fused attention dot partials
    float si0[4], si1[4], sj0[4], sj1[4];
#pragma unroll
    for (int mt = 0; mt < 4; mt++) { si0[mt] = 0.f; si1[mt] = 0.f; sj0[mt] = 0.f; sj1[mt] = 0.f; }

#pragma unroll
    for (int nt = 0; nt < 4; nt++) {
        int c0 = bcol + wn * 32 + nt * 8 + (l & 3) * 2;
        float ai0 = att[c0], ai1 = att[c0 + 1];
        float aj0 = att[NCOLS + c0], aj1 = att[NCOLS + c0 + 1];
#pragma unroll
        for (int mt = 0; mt < 4; mt++) {
            si0[mt] += acc[mt][nt][0] * ai0 + acc[mt][nt][1] * ai1;
            si1[mt] += acc[mt][nt][2] * ai0 + acc[mt][nt][3] * ai1;
            sj0[mt] += acc[mt][nt][0] * aj0 + acc[mt][nt][1] * aj1;
            sj1[mt] += acc[mt][nt][2] * aj0 + acc[mt][nt][3] * aj1;
        }
    }
#pragma unroll
    for (int mt = 0; mt < 4; mt++) {
        si0[mt] += __shfl_xor_sync(0xffffffffu, si0[mt], 1);
        si0[mt] += __shfl_xor_sync(0xffffffffu, si0[mt], 2);
        si1[mt] += __shfl_xor_sync(0xffffffffu, si1[mt], 1);
        si1[mt] += __shfl_xor_sync(0xffffffffu, si1[mt], 2);
        sj0[mt] += __shfl_xor_sync(0xffffffffu, sj0[mt], 1);
        sj0[mt] += __shfl_xor_sync(0xffffffffu, sj0[mt], 2);
        sj1[mt] += __shfl_xor_sync(0xffffffffu, sj1[mt], 1);
        sj1[mt] += __shfl_xor_sync(0xffffffffu, sj1[mt], 2);
    }

#pragma unroll
    for (int mt = 0; mt < 4; mt++) {
        int r0 = brow + wm * 64 + mt * 16 + (l >> 2);
#pragma unroll
        for (int nt = 0; nt < 4; nt++) {
            int c0 = bcol + wn * 32 + nt * 8 + (l & 3) * 2;
            if (r0 < M)
                *(float2*)(Cmat + (size_t)r0 * NCOLS + c0) =
                    make_float2(acc[mt][nt][0], acc[mt][nt][1]);
            if (r0 + 8 < M)
                *(float2*)(Cmat + (size_t)(r0 + 8) * NCOLS + c0) =
                    make_float2(acc[mt][nt][2], acc[mt][nt][3]);
        }
        if ((l & 3) == 0) {
            if (r0 < M) { atomicAdd(&di[r0], si0[mt]); atomicAdd(&dj[r0], sj0[mt]); }
            if (r0 + 8 < M) { atomicAdd(&di[r0 + 8], si1[mt]); atomicAdd(&dj[r0 + 8], sj1[mt]); }
        }
    }
}

// ---------------- fused aggregation (min-issue loop: LDS.64 + f32x2 FMA) ----
// t via blockIdx.y
template <int C>
__global__ void __launch_bounds__(256)
agg_kernel(const float* __restrict__ hBase, size_t strideH,
           const float* __restrict__ bvec,
           const float* __restrict__ diBase, const float* __restrict__ djBase,
           float* __restrict__ muBase) {
    constexpr int PL = C / 32;
    __shared__ uint2 s_pair[8][32];    // (idx, alpha bits)
    int t = blockIdx.y;
    int w = threadIdx.x >> 5;
    int gw = blockIdx.x * 8 + w;
    int lane = threadIdx.x & 31;
    if (gw >= NN) return;
    const float* h = hBase + (size_t)t * strideH;
    const float* di = diBase + (size_t)t * NN;
    const float* dj = djBase + (size_t)t * NN;
    float* mu_out = muBase + (size_t)t * NN * C;

    int beg = g_rowptr[t][gw], end = g_rowptr[t][gw + 1];
    float dvi = di[gw];
    float invdeg = 1.f / (float)(end - beg);
    float bM[PL], bS[PL];
#pragma unroll
    for (int k = 0; k < PL; k++) {
        bM[k] = bvec[lane * PL + k];
        bS[k] = bvec[C + lane * PL + k];
    }
    unsigned long long accMa = 0ull, accMb = 0ull, accSa = 0ull, accSb = 0ull;
    float skl = 0.f;
    const float q = 1.f / (1.f + expf(-(1.f / 15.f)));
    const float logq = logf(q), log1mq = logf(1.f - q);

    for (int base = beg; base < end; base += 32) {
        int n = min(32, end - base);
        if (lane < n) {
            int idx = g_csr_src[t][base + lane];
            float lg = dvi + dj[idx];
            lg = lg > 0.f ? lg : 0.2f * lg;
            float p = 1.f / (1.f + __expf(-lg));
            p = fminf(fmaxf(p, 0.01f), 0.99f);
            float alpha = p * invdeg;
            skl += p * (__logf(p) - logq) + (1.f - p) * (__logf(1.f - p) - log1mq);
            s_pair[w][lane] = make_uint2((unsigned)idx, __float_as_uint(alpha));
        }
        __syncwarp();
        if constexpr (PL == 4) {
#pragma unroll 4
            for (int j = 0; j < n; j++) {
                uint2 pk = s_pair[w][j];
                const float* hr = h + (size_t)pk.x * (2 * C);
                ulonglong2 mr = __ldcg((const ulonglong2*)(hr + lane * 4));
                ulonglong2 sr = __ldcg((const ulonglong2*)(hr + C + lane * 4));
                unsigned long long a2;
                asm("mov.b64 %0, {%1, %1};" : "=l"(a2) : "r"(pk.y));
                ffma2(accMa, mr.x, a2); ffma2(accMb, mr.y, a2);
                ffma2(accSa, sr.x, a2); ffma2(accSb, sr.y, a2);
            }
        } else {
#pragma unroll 4
            for (int j = 0; j < n; j++) {
                uint2 pk = s_pair[w][j];
                const float* hr = h + (size_t)pk.x * (2 * C);
                unsigned long long mr = __ldcg((const unsigned long long*)(hr + lane * 2));
                unsigned long long sr = __ldcg((const unsigned long long*)(hr + C + lane * 2));
                unsigned long long a2;
                asm("mov.b64 %0, {%1, %1};" : "=l"(a2) : "r"(pk.y));
                ffma2(accMa, mr, a2);
                ffma2(accSa, sr, a2);
            }
        }
        __syncwarp();
    }

    float accM[PL], accS[PL];
    asm("mov.b64 {%0, %1}, %2;" : "=f"(accM[0]), "=f"(accM[1]) : "l"(accMa));
    asm("mov.b64 {%0, %1}, %2;" : "=f"(accS[0]), "=f"(accS[1]) : "l"(accSa));
    if constexpr (PL == 4) {
        asm("mov.b64 {%0, %1}, %2;" : "=f"(accM[2]), "=f"(accM[3]) : "l"(accMb));
        asm("mov.b64 {%0, %1}, %2;" : "=f"(accS[2]), "=f"(accS[3]) : "l"(accSb));
    }
#pragma unroll
    for (int k = 0; k < PL; k++) {
        accM[k] += bM[k];
        accS[k] += bS[k];
    }
    if constexpr (PL == 4) {
        *(float4*)(mu_out + (size_t)gw * C + lane * 4) =
            make_float4(accM[0], accM[1], accM[2], accM[3]);
    } else {
        *(float2*)(mu_out + (size_t)gw * C + lane * 2) =
            make_float2(accM[0], accM[1]);
    }
    float kls = 0.f;
#pragma unroll
    for (int k = 0; k < PL; k++) {
        float x = accS[k];
        float sp = fmaxf(x, 0.f) + __logf(1.f + __expf(-fabsf(x)));   // softplus
        float sd = sp + 1e-10f;
        float m = accM[k];
        kls += -__logf(sd) + 0.5f * (sd * sd + m * m) - 0.5f;
    }
#pragma unroll
    for (int off = 16; off; off >>= 1) {
        kls += __shfl_xor_sync(0xffffffffu, kls, off);
        skl += __shfl_xor_sync(0xffffffffu, skl, off);
    }
    if (lane == 0) { atomicAdd(&g_ixz, kls); atomicAdd(&g_skl, skl); }
}

// ---------------- temporal fusion ----------------
__global__ void fuse_relu_kernel(float* __restrict__ mu1) {
    size_t i = (size_t)blockIdx.x * blockDim.x + threadIdx.x;
    const size_t total = (size_t)NN * H1C;
    if (i < total) {
        float a = mu1[i], b = mu1[total + i];
        mu1[i] = fmaxf(a, 0.f);
        mu1[total + i] = fmaxf(0.4f * a + 0.2f * b, 0.f);
    }
}

__global__ void final_kernel(const float* __restrict__ mu2,
                             float* __restrict__ out, int out_size) {
    int i = blockIdx.x * blockDim.x + threadIdx.x;
    const int total = NN * OUTC;
    if (i < total) {
        float a = mu2[i], b = mu2[total + i];
        if (i < out_size) out[i] = a;
        if (total + i < out_size) out[total + i] = 0.4f * a + 0.2f * b;
    }
    if (i == 0) {
        if (2 * total < out_size)     out[2 * total]     = g_ixz / (4.0f * NN);
        if (2 * total + 1 < out_size) out[2 * total + 1] = g_skl / (4.0f * EE);
    }
}

// ---------------- launch ----------------
extern "C" void kernel_launch(void* const* d_in, const int* in_sizes, int n_in,
                              void* d_out, int out_size) {
    const float* x_all = (const float*)d_in[0];
    const int*   ei    = (const int*)d_in[1];
    const float* W1    = (const float*)d_in[2];
    const float* att1  = (const float*)d_in[3];
    const float* b1    = (const float*)d_in[4];
    const float* W2    = (const float*)d_in[5];
    const float* att2  = (const float*)d_in[6];
    const float* b2    = (const float*)d_in[7];
    float* out = (float*)d_out;

    float *p_h0, *p_mu1, *p_mu2, *p_dia, *p_dja;
    cudaGetSymbolAddress((void**)&p_h0, g_h);
    cudaGetSymbolAddress((void**)&p_mu1, g_mu1);
    cudaGetSymbolAddress((void**)&p_mu2, g_mu2);
    cudaGetSymbolAddress((void**)&p_dia, g_dia);
    cudaGetSymbolAddress((void**)&p_dja, g_dja);
    float* p_diL[2] = {p_dia, p_dia + 2 * NN};
    float* p_djL[2] = {p_dja, p_dja + 2 * NN};
    uint32_t *p_B1h, *p_B1l, *p_B2h, *p_B2l;
    cudaGetSymbolAddress((void**)&p_B1h, g_B1h);
    cudaGetSymbolAddress((void**)&p_B1l, g_B1l);
    cudaGetSymbolAddress((void**)&p_B2h, g_B2h);
    cudaGetSymbolAddress((void**)&p_B2l, g_B2l);

    const int GSMEM = 69632;   // A hi/lo only
    static bool attr_done = false;
    if (!attr_done) {
        cudaFuncSetAttribute(gemm_mma<256>, cudaFuncAttributeMaxDynamicSharedMemorySize, GSMEM);
        cudaFuncSetAttribute(gemm_mma<128>, cudaFuncAttributeMaxDynamicSharedMemorySize, GSMEM);
        attr_done = true;
    }

    int gBlocks = (NN + 127) / 128;
    int warpBlocks = (NN + 7) / 8;

    convB_kernel<<<(256 * 64 + 255) / 256, 256>>>(W1, p_B1h, p_B1l, 256);   // 1
    zero_kernel<<<(NN + 255) / 256, 256>>>();                               // 2
    hist2_kernel<<<(2 * EE + 255) / 256, 256>>>(ei);                        // 3
    gemm_mma<256><<<dim3(gBlocks, 2, 2), 256, GSMEM>>>(                      // 4 (profiled)
        x_all, (size_t)NN * FIN, p_B1h, p_B1l, p_h0, (size_t)NN * 256,
        att1, p_diL[0], p_djL[0], NN);
    scan2_kernel<<<2, 1024>>>();                                            // 5
    scatter2_kernel<<<(2 * EE + 255) / 256, 256>>>(ei);                     // 6
    convB_kernel<<<(128 * 64 + 255) / 256, 256>>>(W2, p_B2h, p_B2l, 128);   // 7
    agg_kernel<H1C><<<dim3(warpBlocks, 2), 256>>>(                          // 8
        p_h0, (size_t)NN * 256, b1, p_diL[0], p_djL[0], p_mu1);
    fuse_relu_kernel<<<(NN * H1C + 255) / 256, 256>>>(p_mu1);               // 9
    gemm_mma<128><<<dim3(gBlocks, 1, 2), 256, GSMEM>>>(                      // 10
        p_mu1, (size_t)NN * H1C, p_B2h, p_B2l, p_h0, (size_t)NN * 256,
        att2, p_diL[1], p_djL[1], NN);
    agg_kernel<OUTC><<<dim3(warpBlocks, 2), 256>>>(                         // 11
        p_h0, (size_t)NN * 256, b2, p_diL[1], p_djL[1], p_mu2);
    final_kernel<<<(NN * OUTC + 255) / 256, 256>>>(p_mu2, out, out_size);   // 12
}

// round 15
// speedup vs baseline: 1.1262x; 1.0078x over previous
#include <cuda_runtime.h>
#include <cuda_bf16.h>
#include <stdint.h>
#include <math.h>

#define NN   30000
#define EE   510000
#define TT   2
#define FIN  128
#define H1C  128
#define OUTC 64
#define GEMMBX 235          // (NN+127)/128
#define SCATBX 3985         // (2*EE+255)/256

// ---------------- scratch (device globals; no allocation) ----------------
__device__ float g_h[TT][NN * 256];        // per-snapshot h = x@W (fp32)
__device__ float g_dia[2][TT][NN];         // [layer][t][node] <h, a_i>
__device__ float g_dja[2][TT][NN];         // [layer][t][node] <h, a_j>
__device__ int   g_deg[TT][NN];
__device__ int   g_cursor[TT][NN];
__device__ int   g_rowptr[TT][NN + 1];
__device__ int   g_csr_src[TT][EE];
__device__ float g_mu1[TT][NN * H1C];
__device__ float g_mu2[TT][NN * OUTC];
__device__ float g_ixz;
__device__ float g_skl;
// weights as bf16 hi/lo in per-lane mma-fragment order
__device__ uint32_t g_B1h[256 * 64];
__device__ uint32_t g_B1l[256 * 64];
__device__ uint32_t g_B2h[128 * 64];
__device__ uint32_t g_B2l[128 * 64];

// ---------------- mma.sync + f32x2 helpers ----------------
__device__ __forceinline__ void mma16816(float* c, const uint32_t* a, const uint32_t* b) {
    asm volatile(
        "mma.sync.aligned.m16n8k16.row.col.f32.bf16.bf16.f32 "
        "{%0,%1,%2,%3}, {%4,%5,%6,%7}, {%8,%9}, {%0,%1,%2,%3};"
        : "+f"(c[0]), "+f"(c[1]), "+f"(c[2]), "+f"(c[3])
        : "r"(a[0]), "r"(a[1]), "r"(a[2]), "r"(a[3]), "r"(b[0]), "r"(b[1]));
}
__device__ __forceinline__ void ffma2(unsigned long long& acc, unsigned long long m,
                                      unsigned long long a2) {
    asm("fma.rn.f32x2 %0, %1, %2, %0;" : "+l"(acc) : "l"(m), "l"(a2));
}

// bf16 hi/lo split of W element -> fragment arrays (shared by convB paths)
__device__ __forceinline__ void convB_elem(const float* W, uint32_t* Bh, uint32_t* Bl,
                                           int Ncols, int i) {
    int l = i & 31, r = (i >> 5) & 1, s = (i >> 6) & 7, g = i >> 9;
    int n = g * 8 + (l >> 2);
    int k = s * 16 + (l & 3) * 2 + r * 8;
    float v0 = W[(size_t)k * Ncols + n];
    float v1 = W[(size_t)(k + 1) * Ncols + n];
    __nv_bfloat162 h2 = __floats2bfloat162_rn(v0, v1);
    float rx = v0 - __bfloat162float(h2.x);
    float ry = v1 - __bfloat162float(h2.y);
    __nv_bfloat162 l2 = __floats2bfloat162_rn(rx, ry);
    Bh[i] = *(uint32_t*)&h2;
    Bl[i] = *(uint32_t*)&l2;
}

// ---------------- setup kernels ----------------
__global__ void zero_kernel() {
    int i = blockIdx.x * blockDim.x + threadIdx.x;
    if (i < NN) {
        g_deg[0][i] = 0; g_deg[1][i] = 0;
        g_cursor[0][i] = 0; g_cursor[1][i] = 0;
        g_dia[0][0][i] = 0.f; g_dia[0][1][i] = 0.f;
        g_dia[1][0][i] = 0.f; g_dia[1][1][i] = 0.f;
        g_dja[0][0][i] = 0.f; g_dja[0][1][i] = 0.f;
        g_dja[1][0][i] = 0.f; g_dja[1][1][i] = 0.f;
    }
    if (i == 0) { g_ixz = 0.f; g_skl = 0.f; }
}

__global__ void scan2_kernel() {
    const int P = 30;
    int t = blockIdx.x;
    __shared__ int wsum[32];
    int tid = threadIdx.x, lane = tid & 31, wid = tid >> 5;
    int base = tid * P;
    int loc[P];
    int s = 0;
#pragma unroll
    for (int j = 0; j < P; j++) {
        int idx = base + j;
        int v = (idx < NN) ? g_deg[t][idx] : 0;
        loc[j] = s;
        s += v;
    }
    int inc = s;
#pragma unroll
    for (int o = 1; o < 32; o <<= 1) {
        int y = __shfl_up_sync(0xffffffffu, inc, o);
        if (lane >= o) inc += y;
    }
    if (lane == 31) wsum[wid] = inc;
    __syncthreads();
    if (wid == 0) {
        int w = wsum[lane];
#pragma unroll
        for (int o = 1; o < 32; o <<= 1) {
            int y = __shfl_up_sync(0xffffffffu, w, o);
            if (lane >= o) w += y;
        }
        wsum[lane] = w;
    }
    __syncthreads();
    int off = inc - s + (wid ? wsum[wid - 1] : 0);
#pragma unroll
    for (int j = 0; j < P; j++) {
        int idx = base + j;
        if (idx < NN) g_rowptr[t][idx] = off + loc[j];
    }
    if (tid == 1023) g_rowptr[t][NN] = off + s;
}

// scatter (blocks [0,SCATBX)) ∥ convB2 (blocks [SCATBX, SCATBX+32))
__global__ void scatter_convB2_kernel(const int* __restrict__ ei,
                                      const float* __restrict__ W2,
                                      uint32_t* __restrict__ B2h,
                                      uint32_t* __restrict__ B2l) {
    int bx = blockIdx.x;
    if (bx >= SCATBX) {
        int i = (bx - SCATBX) * 256 + threadIdx.x;
        if (i < 128 * 64) convB_elem(W2, B2h, B2l, 128, i);
        return;
    }
    int i = bx * 256 + threadIdx.x;
    if (i < 2 * EE) {
        int t = (i >= EE) ? 1 : 0;
        int e = i - t * EE;
        const int* src = ei + (size_t)t * 2 * EE;
        const int* dst = src + EE;
        int d = dst[e];
        int pos = g_rowptr[t][d] + atomicAdd(&g_cursor[t][d], 1);
        g_csr_src[t][pos] = src[e];
    }
}

// W fp32 [K=128, Ncols] -> bf16 hi/lo fragments (per-lane order)
__global__ void convB_kernel(const float* __restrict__ W,
                             uint32_t* __restrict__ Bh,
                             uint32_t* __restrict__ Bl, int Ncols) {
    int i = blockIdx.x * blockDim.x + threadIdx.x;
    if (i < Ncols * 64) convB_elem(W, Bh, Bl, Ncols, i);
}

// ---------------- HMMA GEMM + fused dots, het-grid hist (t via blockIdx.z) --
// blocks x<gemmBX: GEMM; x>=gemmBX: edge histogram (MEGA1 only)
template <int NCOLS>
__global__ void __launch_bounds__(256, 2)
gemm_mma(const float* __restrict__ Abase, size_t strideA,
         const uint32_t* __restrict__ Bh, const uint32_t* __restrict__ Bl,
         float* __restrict__ Cbase, size_t strideC,
         const float* __restrict__ att,
         float* __restrict__ diBase, float* __restrict__ djBase, int M,
         const int* __restrict__ ei, int gemmBX) {
    extern __shared__ char smem[];
    if ((int)blockIdx.x >= gemmBX) {
        // histogram side-car (grid y,z each in {0,1} for MEGA1)
        int chunk = ((int)blockIdx.x - gemmBX) * 4 + (int)blockIdx.y * 2 + (int)blockIdx.z;
        int i = chunk * 256 + (int)threadIdx.x;
        if (i < 2 * EE) {
            int t = (i >= EE) ? 1 : 0;
            int e = i - t * EE;
            int d = ei[(size_t)t * 2 * EE + EE + e];
            atomicAdd(&g_deg[t][d], 1);
        }
        return;
    }
    const int AL_OFF = 34816;
    int tid = threadIdx.x, wid = tid >> 5, l = tid & 31;
    int brow = blockIdx.x * 128, bcol = blockIdx.y * 128;
    int tz = blockIdx.z;
    const float* A = Abase + (size_t)tz * strideA;
    float* Cmat = Cbase + (size_t)tz * strideC;
    float* di = diBase + (size_t)tz * NN;
    float* dj = djBase + (size_t)tz * NN;
    const uint32_t* gBh = Bh + (size_t)blockIdx.y * 16 * 512;
    const uint32_t* gBl = Bl + (size_t)blockIdx.y * 16 * 512;

    for (int i = tid; i < 128 * 64; i += 256) {
        int row = i >> 6, kp = i & 63;
        int gr = brow + row;
        float2 v = make_float2(0.f, 0.f);
        if (gr < M) v = *(const float2*)(A + (size_t)gr * 128 + kp * 2);
        __nv_bfloat162 h2 = __floats2bfloat162_rn(v.x, v.y);
        float rx = v.x - __bfloat162float(h2.x);
        float ry = v.y - __bfloat162float(h2.y);
        __nv_bfloat162 l2 = __floats2bfloat162_rn(rx, ry);
        int hoff = row * 136 + kp * 2;
        *(uint32_t*)(smem + hoff * 2) = *(uint32_t*)&h2;
        *(uint32_t*)(smem + AL_OFF + hoff * 2) = *(uint32_t*)&l2;
    }
    __syncthreads();

    int wm = wid >> 2, wn = wid & 3;
    float acc[4][4][4];
#pragma unroll
    for (int mt = 0; mt < 4; mt++)
#pragma unroll
        for (int nt = 0; nt < 4; nt++)
#pragma unroll
            for (int k = 0; k < 4; k++) acc[mt][nt][k] = 0.f;

    int arow = wm * 64 + (l >> 2);
    int acol = (l & 3) * 2;

    for (int s = 0; s < 8; s++) {
        uint32_t bH[4][2], bL[4][2];
#pragma unroll
        for (int nt = 0; nt < 4; nt++) {
            int g = wn * 4 + nt;
            int base = ((g * 8 + s) * 2) * 32 + l;
            bH[nt][0] = gBh[base]; bH[nt][1] = gBh[base + 32];
            bL[nt][0] = gBl[base]; bL[nt][1] = gBl[base + 32];
        }
        uint32_t aH[4][4], aL[4][4];
#pragma unroll
        for (int mt = 0; mt < 4; mt++) {
            int r0 = arow + mt * 16;
            int c0 = s * 16 + acol;
            int o00 = (r0 * 136 + c0) * 2;
            int o10 = ((r0 + 8) * 136 + c0) * 2;
            aH[mt][0] = *(uint32_t*)(smem + o00);
            aH[mt][1] = *(uint32_t*)(smem + o10);
            aH[mt][2] = *(uint32_t*)(smem + o00 + 16);
            aH[mt][3] = *(uint32_t*)(smem + o10 + 16);
            aL[mt][0] = *(uint32_t*)(smem + AL_OFF + o00);
            aL[mt][1] = *(uint32_t*)(smem + AL_OFF + o10);
            aL[mt][2] = *(uint32_t*)(smem + AL_OFF + o00 + 16);
            aL[mt][3] = *(uint32_t*)(smem + AL_OFF + o10 + 16);
        }
#pragma unroll
        for (int mt = 0; mt < 4; mt++)
#pragma unroll
            for (int nt = 0; nt < 4; nt++) {
                mma16816(acc[mt][nt], aH[mt], bH[nt]);
                mma16816(acc[mt][nt], aH[mt], bL[nt]);
                mma16816(acc[mt][nt], aL[mt], bH[nt]);
            }
    }

    float si0[4], si1[4], sj0[4], sj1[4];
#pragma unroll
    for (int mt = 0; mt < 4; mt++) { si0[mt] = 0.f; si1[mt] = 0.f; sj0[mt] = 0.f; sj1[mt] = 0.f; }

#pragma unroll
    for (int nt = 0; nt < 4; nt++) {
        int c0 = bcol + wn * 32 + nt * 8 + (l & 3) * 2;
        float ai0 = att[c0], ai1 = att[c0 + 1];
        float aj0 = att[NCOLS + c0], aj1 = att[NCOLS + c0 + 1];
#pragma unroll
        for (int mt = 0; mt < 4; mt++) {
            si0[mt] += acc[mt][nt][0] * ai0 + acc[mt][nt][1] * ai1;
            si1[mt] += acc[mt][nt][2] * ai0 + acc[mt][nt][3] * ai1;
            sj0[mt] += acc[mt][nt][0] * aj0 + acc[mt][nt][1] * aj1;
            sj1[mt] += acc[mt][nt][2] * aj0 + acc[mt][nt][3] * aj1;
        }
    }
#pragma unroll
    for (int mt = 0; mt < 4; mt++) {
        si0[mt] += __shfl_xor_sync(0xffffffffu, si0[mt], 1);
        si0[mt] += __shfl_xor_sync(0xffffffffu, si0[mt], 2);
        si1[mt] += __shfl_xor_sync(0xffffffffu, si1[mt], 1);
        si1[mt] += __shfl_xor_sync(0xffffffffu, si1[mt], 2);
        sj0[mt] += __shfl_xor_sync(0xffffffffu, sj0[mt], 1);
        sj0[mt] += __shfl_xor_sync(0xffffffffu, sj0[mt], 2);
        sj1[mt] += __shfl_xor_sync(0xffffffffu, sj1[mt], 1);
        sj1[mt] += __shfl_xor_sync(0xffffffffu, sj1[mt], 2);
    }

#pragma unroll
    for (int mt = 0; mt < 4; mt++) {
        int r0 = brow + wm * 64 + mt * 16 + (l >> 2);
#pragma unroll
        for (int nt = 0; nt < 4; nt++) {
            int c0 = bcol + wn * 32 + nt * 8 + (l & 3) * 2;
            if (r0 < M)
                *(float2*)(Cmat + (size_t)r0 * NCOLS + c0) =
                    make_float2(acc[mt][nt][0], acc[mt][nt][1]);
            if (r0 + 8 < M)
                *(float2*)(Cmat + (size_t)(r0 + 8) * NCOLS + c0) =
                    make_float2(acc[mt][nt][2], acc[mt][nt][3]);
        }
        if ((l & 3) == 0) {
            if (r0 < M) { atomicAdd(&di[r0], si0[mt]); atomicAdd(&dj[r0], sj0[mt]); }
            if (r0 + 8 < M) { atomicAdd(&di[r0 + 8], si1[mt]); atomicAdd(&dj[r0 + 8], sj1[mt]); }
        }
    }
}

// ---------------- fused aggregation (min-issue loop: LDS.64 + f32x2 FMA) ----
// t via blockIdx.y
template <int C>
__global__ void __launch_bounds__(256)
agg_kernel(const float* __restrict__ hBase, size_t strideH,
           const float* __restrict__ bvec,
           const float* __restrict__ diBase, const float* __restrict__ djBase,
           float* __restrict__ muBase) {
    constexpr int PL = C / 32;
    __shared__ uint2 s_pair[8][32];    // (idx, alpha bits)
    int t = blockIdx.y;
    int w = threadIdx.x >> 5;
    int gw = blockIdx.x * 8 + w;
    int lane = threadIdx.x & 31;
    if (gw >= NN) return;
    const float* h = hBase + (size_t)t * strideH;
    const float* di = diBase + (size_t)t * NN;
    const float* dj = djBase + (size_t)t * NN;
    float* mu_out = muBase + (size_t)t * NN * C;

    int beg = g_rowptr[t][gw], end = g_rowptr[t][gw + 1];
    float dvi = di[gw];
    float invdeg = 1.f / (float)(end - beg);
    float bM[PL], bS[PL];
#pragma unroll
    for (int k = 0; k < PL; k++) {
        bM[k] = bvec[lane * PL + k];
        bS[k] = bvec[C + lane * PL + k];
    }
    unsigned long long accMa = 0ull, accMb = 0ull, accSa = 0ull, accSb = 0ull;
    float skl = 0.f;
    const float q = 1.f / (1.f + expf(-(1.f / 15.f)));
    const float logq = logf(q), log1mq = logf(1.f - q);

    for (int base = beg; base < end; base += 32) {
        int n = min(32, end - base);
        if (lane < n) {
            int idx = g_csr_src[t][base + lane];
            float lg = dvi + dj[idx];
            lg = lg > 0.f ? lg : 0.2f * lg;
            float p = 1.f / (1.f + __expf(-lg));
            p = fminf(fmaxf(p, 0.01f), 0.99f);
            float alpha = p * invdeg;
            skl += p * (__logf(p) - logq) + (1.f - p) * (__logf(1.f - p) - log1mq);
            s_pair[w][lane] = make_uint2((unsigned)idx, __float_as_uint(alpha));
        }
        __syncwarp();
        if constexpr (PL == 4) {
#pragma unroll 4
            for (int j = 0; j < n; j++) {
                uint2 pk = s_pair[w][j];
                const float* hr = h + (size_t)pk.x * (2 * C);
                ulonglong2 mr = __ldcg((const ulonglong2*)(hr + lane * 4));
                ulonglong2 sr = __ldcg((const ulonglong2*)(hr + C + lane * 4));
                unsigned long long a2;
                asm("mov.b64 %0, {%1, %1};" : "=l"(a2) : "r"(pk.y));
                ffma2(accMa, mr.x, a2); ffma2(accMb, mr.y, a2);
                ffma2(accSa, sr.x, a2); ffma2(accSb, sr.y, a2);
            }
        } else {
#pragma unroll 4
            for (int j = 0; j < n; j++) {
                uint2 pk = s_pair[w][j];
                const float* hr = h + (size_t)pk.x * (2 * C);
                unsigned long long mr = __ldcg((const unsigned long long*)(hr + lane * 2));
                unsigned long long sr = __ldcg((const unsigned long long*)(hr + C + lane * 2));
                unsigned long long a2;
                asm("mov.b64 %0, {%1, %1};" : "=l"(a2) : "r"(pk.y));
                ffma2(accMa, mr, a2);
                ffma2(accSa, sr, a2);
            }
        }
        __syncwarp();
    }

    float accM[PL], accS[PL];
    asm("mov.b64 {%0, %1}, %2;" : "=f"(accM[0]), "=f"(accM[1]) : "l"(accMa));
    asm("mov.b64 {%0, %1}, %2;" : "=f"(accS[0]), "=f"(accS[1]) : "l"(accSa));
    if constexpr (PL == 4) {
        asm("mov.b64 {%0, %1}, %2;" : "=f"(accM[2]), "=f"(accM[3]) : "l"(accMb));
        asm("mov.b64 {%0, %1}, %2;" : "=f"(accS[2]), "=f"(accS[3]) : "l"(accSb));
    }
#pragma unroll
    for (int k = 0; k < PL; k++) {
        accM[k] += bM[k];
        accS[k] += bS[k];
    }
    if constexpr (PL == 4) {
        *(float4*)(mu_out + (size_t)gw * C + lane * 4) =
            make_float4(accM[0], accM[1], accM[2], accM[3]);
    } else {
        *(float2*)(mu_out + (size_t)gw * C + lane * 2) =
            make_float2(accM[0], accM[1]);
    }
    float kls = 0.f;
#pragma unroll
    for (int k = 0; k < PL; k++) {
        float x = accS[k];
        float sp = fmaxf(x, 0.f) + __logf(1.f + __expf(-fabsf(x)));   // softplus
        float sd = sp + 1e-10f;
        float m = accM[k];
        kls += -__logf(sd) + 0.5f * (sd * sd + m * m) - 0.5f;
    }
#pragma unroll
    for (int off = 16; off; off >>= 1) {
        kls += __shfl_xor_sync(0xffffffffu, kls, off);
        skl += __shfl_xor_sync(0xffffffffu, skl, off);
    }
    if (lane == 0) { atomicAdd(&g_ixz, kls); atomicAdd(&g_skl, skl); }
}

// ---------------- temporal fusion ----------------
__global__ void fuse_relu_kernel(float* __restrict__ mu1) {
    size_t i = (size_t)blockIdx.x * blockDim.x + threadIdx.x;
    const size_t total = (size_t)NN * H1C;
    if (i < total) {
        float a = mu1[i], b = mu1[total + i];
        mu1[i] = fmaxf(a, 0.f);
        mu1[total + i] = fmaxf(0.4f * a + 0.2f * b, 0.f);
    }
}

__global__ void final_kernel(const float* __restrict__ mu2,
                             float* __restrict__ out, int out_size) {
    int i = blockIdx.x * blockDim.x + threadIdx.x;
    const int total = NN * OUTC;
    if (i < total) {
        float a = mu2[i], b = mu2[total + i];
        if (i < out_size) out[i] = a;
        if (total + i < out_size) out[total + i] = 0.4f * a + 0.2f * b;
    }
    if (i == 0) {
        if (2 * total < out_size)     out[2 * total]     = g_ixz / (4.0f * NN);
        if (2 * total + 1 < out_size) out[2 * total + 1] = g_skl / (4.0f * EE);
    }
}

// ---------------- launch ----------------
extern "C" void kernel_launch(void* const* d_in, const int* in_sizes, int n_in,
                              void* d_out, int out_size) {
    const float* x_all = (const float*)d_in[0];
    const int*   ei    = (const int*)d_in[1];
    const float* W1    = (const float*)d_in[2];
    const float* att1  = (const float*)d_in[3];
    const float* b1    = (const float*)d_in[4];
    const float* W2    = (const float*)d_in[5];
    const float* att2  = (const float*)d_in[6];
    const float* b2    = (const float*)d_in[7];
    float* out = (float*)d_out;

    float *p_h0, *p_mu1, *p_mu2, *p_dia, *p_dja;
    cudaGetSymbolAddress((void**)&p_h0, g_h);
    cudaGetSymbolAddress((void**)&p_mu1, g_mu1);
    cudaGetSymbolAddress((void**)&p_mu2, g_mu2);
    cudaGetSymbolAddress((void**)&p_dia, g_dia);
    cudaGetSymbolAddress((void**)&p_dja, g_dja);
    float* p_diL[2] = {p_dia, p_dia + 2 * NN};
    float* p_djL[2] = {p_dja, p_dja + 2 * NN};
    uint32_t *p_B1h, *p_B1l, *p_B2h, *p_B2l;
    cudaGetSymbolAddress((void**)&p_B1h, g_B1h);
    cudaGetSymbolAddress((void**)&p_B1l, g_B1l);
    cudaGetSymbolAddress((void**)&p_B2h, g_B2h);
    cudaGetSymbolAddress((void**)&p_B2l, g_B2l);

    const int GSMEM = 69632;   // A hi/lo only
    static bool attr_done = false;
    if (!attr_done) {
        cudaFuncSetAttribute(gemm_mma<256>, cudaFuncAttributeMaxDynamicSharedMemorySize, GSMEM);
        cudaFuncSetAttribute(gemm_mma<128>, cudaFuncAttributeMaxDynamicSharedMemorySize, GSMEM);
        attr_done = true;
    }

    int warpBlocks = (NN + 7) / 8;
    const int HISTBX = 997;    // 997*4 blocks * 256 >= 2*EE

    convB_kernel<<<(256 * 64 + 255) / 256, 256>>>(W1, p_B1h, p_B1l, 256);    // 1
    zero_kernel<<<(NN + 255) / 256, 256>>>();                                // 2
    // 3: MEGA1 — gemm256 (t0,t1) with histogram side-car blocks
    gemm_mma<256><<<dim3(GEMMBX + HISTBX, 2, 2), 256, GSMEM>>>(
        x_all, (size_t)NN * FIN, p_B1h, p_B1l, p_h0, (size_t)NN * 256,
        att1, p_diL[0], p_djL[0], NN, ei, GEMMBX);
    scan2_kernel<<<2, 1024>>>();                                             // 4
    scatter_convB2_kernel<<<SCATBX + 32, 256>>>(ei, W2, p_B2h, p_B2l);       // 5
    agg_kernel<H1C><<<dim3(warpBlocks, 2), 256>>>(                           // 6
        p_h0, (size_t)NN * 256, b1, p_diL[0], p_djL[0], p_mu1);
    fuse_relu_kernel<<<(NN * H1C + 255) / 256, 256>>>(p_mu1);                // 7
    gemm_mma<128><<<dim3(GEMMBX, 1, 2), 256, GSMEM>>>(                        // 8
        p_mu1, (size_t)NN * H1C, p_B2h, p_B2l, p_h0, (size_t)NN * 256,
        att2, p_diL[1], p_djL[1], NN, ei, GEMMBX);
    agg_kernel<OUTC><<<dim3(warpBlocks, 2), 256>>>(                          // 9
        p_h0, (size_t)NN * 256, b2, p_diL[1], p_djL[1], p_mu2);
    final_kernel<<<(NN * OUTC + 255) / 256, 256>>>(p_mu2, out, out_size);    // 10
}